// round 4
// baseline (speedup 1.0000x reference)
#include <cuda_runtime.h>

// NSSTDecomposition: 3 grouped conv banks + lowpass channel.
// Input : rgb_image (4,3,512,512) f32, f0 (12,1,11,11), f1 (24,1,15,15), f2 (48,1,19,19)
// Output: (4,87,512,512) f32, per color c: [4 dirs s0][8 dirs s1][16 dirs s2][low]
//
// R3: packed fp32x2 FMAs (fma.rn.f32x2). Direction-pair accumulators; weights
// transposed in smem so a direction pair is one LDS.64; input tile duplicated
// ({v,v}) so the broadcast multiplicand is one LDS.64. Halves fma-pipe instrs.

#define TILE   32
#define HALO   9                 // max radius (19x19 -> 9)
#define IN_DIM (TILE + 2*HALO)   // 50
#define IMG_W  512
#define IMG_HW (512*512)

typedef unsigned long long u64;

// Lowpass scratch: (4,3,128,128) f32  (static device array: allocation-free)
__device__ float g_low[4*3*128*128];

__device__ __forceinline__ u64 ffma2(u64 a, u64 b, u64 c) {
    u64 d;
    asm("fma.rn.f32x2 %0, %1, %2, %3;" : "=l"(d) : "l"(a), "l"(b), "l"(c));
    return d;
}

// ---------------------------------------------------------------------------
// Per-scale conv over a 32x32 tile. tx = tid&31, ty = tid>>5 (0..7); each
// thread owns 4 rows (y = ty + j*8) and DC direction accumulators held as
// DC/2 packed f32x2 pairs.
//   s_in2 : duplicated input tile, element i = {in[i], in[i]}      (u64)
//   s_w2  : transposed weights, [tap][d] pairs -> {w_d, w_{d+1}}   (u64)
// ---------------------------------------------------------------------------
template<int K, int D, int DC>
__device__ __forceinline__ void conv_scale(
    const u64* __restrict__ s_in2,
    const u64* __restrict__ s_w2,
    float* __restrict__ out, int out_base,
    int tx, int ty, int x0, int y0)
{
    const int R   = K / 2;
    const int off = HALO - R;

    #pragma unroll
    for (int d0 = 0; d0 < D; d0 += DC) {
        u64 acc[4][DC/2];
        #pragma unroll
        for (int j = 0; j < 4; j++)
            #pragma unroll
            for (int p = 0; p < DC/2; p++) acc[j][p] = 0ull;   // {0.f,0.f}

        for (int ky = 0; ky < K; ky++) {
            const u64* wrow = s_w2 + (ky * K) * (D/2) + (d0/2);
            const u64* r0   = s_in2 + (ty + off + ky) * IN_DIM + (tx + off);
            #pragma unroll
            for (int kx = 0; kx < K; kx++) {
                u64 wr[DC/2];
                #pragma unroll
                for (int p = 0; p < DC/2; p++)
                    wr[p] = wrow[kx * (D/2) + p];
                #pragma unroll
                for (int j = 0; j < 4; j++) {
                    u64 v = r0[j * (8 * IN_DIM) + kx];          // {v, v}
                    #pragma unroll
                    for (int p = 0; p < DC/2; p++)
                        acc[j][p] = ffma2(v, wr[p], acc[j][p]);
                }
            }
        }

        // Coalesced writes: consecutive tx -> consecutive x.
        #pragma unroll
        for (int j = 0; j < 4; j++) {
            const int y = y0 + ty + j * 8;
            const int x = x0 + tx;
            #pragma unroll
            for (int p = 0; p < DC/2; p++) {
                float2 a = *reinterpret_cast<float2*>(&acc[j][p]);
                out[out_base + (d0 + 2*p    ) * IMG_HW + y * IMG_W + x] = a.x;
                out[out_base + (d0 + 2*p + 1) * IMG_HW + y * IMG_W + x] = a.y;
            }
        }
    }
}

__global__ void __launch_bounds__(256)
nsst_conv_kernel(const float* __restrict__ img,
                 const float* __restrict__ f0,
                 const float* __restrict__ f1,
                 const float* __restrict__ f2,
                 float* __restrict__ out)
{
    __shared__ u64 s_in2[IN_DIM * IN_DIM];      // 2500 u64 = 20 KB (dup input)
    __shared__ u64 s_w2[16 * 19 * 19 / 2];      // 2888 u64 = 23.1 KB (max scale)

    const int tid = threadIdx.x;
    const int bz  = blockIdx.z;
    const int b   = bz / 3;
    const int c   = bz % 3;
    const int x0  = blockIdx.x * TILE;
    const int y0  = blockIdx.y * TILE;

    // Load 50x50 input tile, duplicated {v,v}, zero padding ("same" conv).
    const float* src = img + (b * 3 + c) * IMG_HW;
    float2* in2f = reinterpret_cast<float2*>(s_in2);
    for (int idx = tid; idx < IN_DIM * IN_DIM; idx += 256) {
        int iy = idx / IN_DIM;
        int ix = idx - iy * IN_DIM;
        int gy = y0 + iy - HALO;
        int gx = x0 + ix - HALO;
        float v = 0.0f;
        if ((unsigned)gy < (unsigned)IMG_W && (unsigned)gx < (unsigned)IMG_W)
            v = src[gy * IMG_W + gx];
        in2f[idx] = make_float2(v, v);
    }

    const int tx = tid & 31;
    const int ty = tid >> 5;
    const int ch_base = b * 87 + c * 29;
    float* wt = reinterpret_cast<float*>(s_w2);

    // ---- scale 0: 4 dirs, 11x11 ----
    {
        const float* f = f0 + c * 4 * 121;   // group slice for this color
        for (int i = tid; i < 4 * 121; i += 256) {
            int d = i / 121, tap = i - d * 121;
            wt[tap * 4 + d] = f[i];          // transpose: [tap][d]
        }
        __syncthreads();                     // covers s_in2 too
        conv_scale<11, 4, 4>(s_in2, s_w2, out, (ch_base + 0) * IMG_HW, tx, ty, x0, y0);
        __syncthreads();
    }
    // ---- scale 1: 8 dirs, 15x15 ----
    {
        const float* f = f1 + c * 8 * 225;
        for (int i = tid; i < 8 * 225; i += 256) {
            int d = i / 225, tap = i - d * 225;
            wt[tap * 8 + d] = f[i];
        }
        __syncthreads();
        conv_scale<15, 8, 8>(s_in2, s_w2, out, (ch_base + 4) * IMG_HW, tx, ty, x0, y0);
        __syncthreads();
    }
    // ---- scale 2: 16 dirs, 19x19 ----
    {
        const float* f = f2 + c * 16 * 361;
        for (int i = tid; i < 16 * 361; i += 256) {
            int d = i / 361, tap = i - d * 361;
            wt[tap * 16 + d] = f[i];
        }
        __syncthreads();
        conv_scale<19, 16, 8>(s_in2, s_w2, out, (ch_base + 12) * IMG_HW, tx, ty, x0, y0);
    }
}

// ---------------------------------------------------------------------------
// Lowpass: 4x4 box mean -> (bc,128,128)
// ---------------------------------------------------------------------------
__global__ void __launch_bounds__(256)
nsst_downsample_kernel(const float* __restrict__ img)
{
    int idx = blockIdx.x * 256 + threadIdx.x;   // 12*128*128 = 196608
    if (idx >= 4 * 3 * 128 * 128) return;
    int X  = idx & 127;
    int Y  = (idx >> 7) & 127;
    int bc = idx >> 14;
    const float* src = img + bc * IMG_HW + (Y * 4) * IMG_W + X * 4;
    float s = 0.0f;
    #pragma unroll
    for (int i = 0; i < 4; i++) {
        float4 r = *reinterpret_cast<const float4*>(src + i * IMG_W);
        s += r.x + r.y + r.z + r.w;
    }
    g_low[idx] = s * (1.0f / 16.0f);
}

// ---------------------------------------------------------------------------
// Bilinear upsample 128->512, half-pixel centers, clamp-to-edge
// (== jax.image.resize 'linear' incl. its edge renormalization).
// ---------------------------------------------------------------------------
__global__ void __launch_bounds__(256)
nsst_upsample_kernel(float* __restrict__ out)
{
    int idx = blockIdx.x * 256 + threadIdx.x;   // 12*512*512 = 3145728
    if (idx >= 4 * 3 * IMG_HW) return;
    int x  = idx & 511;
    int y  = (idx >> 9) & 511;
    int bc = idx >> 18;
    int b  = bc / 3;
    int c  = bc % 3;

    float sy = y * 0.25f - 0.375f;   // (y+0.5)/4 - 0.5
    float sx = x * 0.25f - 0.375f;
    int iy0 = (int)floorf(sy);
    int ix0 = (int)floorf(sx);
    float fy = sy - (float)iy0;
    float fx = sx - (float)ix0;
    int y0c = max(0, min(127, iy0));
    int y1c = max(0, min(127, iy0 + 1));
    int x0c = max(0, min(127, ix0));
    int x1c = max(0, min(127, ix0 + 1));

    const float* L = g_low + bc * 128 * 128;
    float v00 = L[y0c * 128 + x0c];
    float v01 = L[y0c * 128 + x1c];
    float v10 = L[y1c * 128 + x0c];
    float v11 = L[y1c * 128 + x1c];
    float top = v00 + fx * (v01 - v00);
    float bot = v10 + fx * (v11 - v10);
    float val = top + fy * (bot - top);

    out[((b * 87 + c * 29 + 28) * IMG_W + y) * IMG_W + x] = val;
}

// ---------------------------------------------------------------------------
extern "C" void kernel_launch(void* const* d_in, const int* in_sizes, int n_in,
                              void* d_out, int out_size)
{
    const float* img = (const float*)d_in[0];
    const float* f0  = (const float*)d_in[1];
    const float* f1  = (const float*)d_in[2];
    const float* f2  = (const float*)d_in[3];
    float* out = (float*)d_out;

    dim3 grid(IMG_W / TILE, IMG_W / TILE, 4 * 3);   // (16,16,12)
    nsst_conv_kernel<<<grid, 256>>>(img, f0, f1, f2, out);

    nsst_downsample_kernel<<<(4 * 3 * 128 * 128 + 255) / 256, 256>>>(img);
    nsst_upsample_kernel<<<(4 * 3 * IMG_HW + 255) / 256, 256>>>(out);
}

// round 8
// speedup vs baseline: 4.2938x; 4.2938x over previous
#include <cuda_runtime.h>
#include <cstdint>

// NSSTDecomposition via mma.sync tf32 implicit GEMM (sm_80+ PTX, no tcgen05).
// D[pixels, 32 dirs] = A[pixels, K=456] x W^T ; all 28 filters zero-extended to
// a 19(dy) x 24(dx-padded) window. A read from a smem window tile on the fly
// (implicit im2col); B staged in smem in pre-computed m16n8k8 fragment order.

#define IMG_W   512
#define IMG_HW  (512*512)
#define WROWS   22
#define WCOLS   152            // 128 + 2*9 halo + dx-pad, 8-aligned
#define NG      57             // K groups of 8: 19 dy * 3 dx-blocks
#define SMEM_B_BYTES   (NG*4*64*4)              // 58368
#define SMEM_WIN_OFF   SMEM_B_BYTES
#define SMEM_TOTAL     (SMEM_B_BYTES + WROWS*WCOLS*4)   // 71744

// scratch (allocation-free)
__device__ float g_low[4*3*128*128];
__device__ float g_bfrag[3*NG*4*64];   // [c][g][nt][lane*2 + r], tf32 bits

__device__ __forceinline__ uint32_t f2tf32(float v) {
    uint32_t b; asm("cvt.rna.tf32.f32 %0, %1;" : "=r"(b) : "f"(v)); return b;
}

__device__ __forceinline__ void mma_tf32(float& d0, float& d1, float& d2, float& d3,
                                         uint32_t a0, uint32_t a1, uint32_t a2, uint32_t a3,
                                         uint32_t b0, uint32_t b1) {
    asm volatile("mma.sync.aligned.m16n8k8.row.col.f32.tf32.tf32.f32 "
                 "{%0,%1,%2,%3}, {%4,%5,%6,%7}, {%8,%9}, {%0,%1,%2,%3};"
                 : "+f"(d0), "+f"(d1), "+f"(d2), "+f"(d3)
                 : "r"(a0), "r"(a1), "r"(a2), "r"(a3), "r"(b0), "r"(b1));
}

// ---------------------------------------------------------------------------
// Prep: weights -> tf32 fragment image. For (c, g, nt, lane, r):
//   n = nt*8 + lane/4 ; k = g*8 + (lane%3bits..) ; b_r = B[k + r*4][n] = W[n][k]
// with k -> (dy = k/24, dx = k%24), filters zero-extended (11x11 @ +4, 15x15 @ +2).
// ---------------------------------------------------------------------------
__global__ void __launch_bounds__(256)
nsst_prep(const float* __restrict__ f0, const float* __restrict__ f1,
          const float* __restrict__ f2)
{
    int i = blockIdx.x * 256 + threadIdx.x;        // 3*57*4*64 = 43776
    if (i >= 3 * NG * 4 * 64) return;
    int r    = i & 1;
    int l    = (i >> 1) & 31;
    int nt   = (i >> 6) & 3;
    int rest = i >> 8;                              // c*NG + g
    int g    = rest % NG;
    int c    = rest / NG;

    int n  = nt * 8 + (l >> 2);
    int kl = (l & 3) + r * 4;
    int dy = g / 3;
    int dx = (g % 3) * 8 + kl;

    float val = 0.0f;
    if (dx < 19 && n < 28) {
        if (n < 4) {
            int ky = dy - 4, kx = dx - 4;
            if ((unsigned)ky < 11u && (unsigned)kx < 11u)
                val = f0[(c*4 + n)*121 + ky*11 + kx];
        } else if (n < 12) {
            int ky = dy - 2, kx = dx - 2;
            if ((unsigned)ky < 15u && (unsigned)kx < 15u)
                val = f1[(c*8 + (n-4))*225 + ky*15 + kx];
        } else {
            val = f2[(c*16 + (n-12))*361 + dy*19 + dx];
        }
    }
    g_bfrag[i] = __uint_as_float(f2tf32(val));
}

// ---------------------------------------------------------------------------
// Conv: grid (4 x-tiles, 128 y-quads, 12 bc), 256 threads = 8 warps.
// Warp w: y-row = w/2, x-half = (w%2)*64; M=64 (4 m16 tiles) x N=32 (4 n8 tiles).
// ---------------------------------------------------------------------------
__global__ void __launch_bounds__(256)
nsst_mma_conv(const float* __restrict__ img, float* __restrict__ out)
{
    extern __shared__ char smem[];
    float*    s_b   = (float*)smem;
    uint32_t* s_win = (uint32_t*)(smem + SMEM_WIN_OFF);

    const int tid = threadIdx.x;
    const int l   = tid & 31;
    const int w   = tid >> 5;
    const int x0  = blockIdx.x * 128;
    const int y0  = blockIdx.y * 4;
    const int bz  = blockIdx.z, b = bz / 3, c = bz % 3;

    // stage B fragments (linear vectorized copy)
    {
        const float4* bs = (const float4*)(g_bfrag + (size_t)c * NG * 4 * 64);
        float4* bd = (float4*)s_b;
        for (int i = tid; i < NG * 4 * 16; i += 256) bd[i] = bs[i];
    }
    // stage window, tf32-rounded, zero-padded (covers halo + dx pad)
    {
        const float* src = img + (size_t)bz * IMG_HW;
        for (int i = tid; i < WROWS * WCOLS; i += 256) {
            int iy = i / WCOLS, ix = i - iy * WCOLS;
            int gy = y0 + iy - 9, gx = x0 + ix - 9;
            float v = 0.0f;
            if ((unsigned)gy < 512u && (unsigned)gx < 512u) v = src[gy * IMG_W + gx];
            s_win[i] = f2tf32(v);
        }
    }
    __syncthreads();

    const int row_w = w >> 1;
    const int xoff  = (w & 1) * 64;

    float acc[4][4][4];
    #pragma unroll
    for (int mt = 0; mt < 4; mt++)
        #pragma unroll
        for (int nt = 0; nt < 4; nt++)
            #pragma unroll
            for (int q = 0; q < 4; q++) acc[mt][nt][q] = 0.0f;

    const uint32_t* wbase = s_win + row_w * WCOLS + xoff + (l >> 2);
    const uint2*    bfp   = (const uint2*)s_b + l;

    #pragma unroll 1
    for (int g = 0; g < NG; g++) {
        int dy  = g / 3;
        int dxb = g - dy * 3;
        const uint32_t* wr = wbase + dy * WCOLS + dxb * 8 + (l & 3);

        uint2 bf[4];
        #pragma unroll
        for (int nt = 0; nt < 4; nt++) bf[nt] = bfp[(g * 4 + nt) * 32];

        #pragma unroll
        for (int mt = 0; mt < 4; mt++) {
            uint32_t a0 = wr[mt * 16];
            uint32_t a2 = wr[mt * 16 + 4];
            uint32_t a1 = wr[mt * 16 + 8];
            uint32_t a3 = wr[mt * 16 + 12];
            #pragma unroll
            for (int nt = 0; nt < 4; nt++)
                mma_tf32(acc[mt][nt][0], acc[mt][nt][1], acc[mt][nt][2], acc[mt][nt][3],
                         a0, a1, a2, a3, bf[nt].x, bf[nt].y);
        }
    }

    // epilogue: D frag c0:(row,col2) c1:(row,col2+1) c2:(row+8,col2) c3:(row+8,col2+1)
    const int chbase = b * 87 + c * 29;
    const int y = y0 + row_w;
    #pragma unroll
    for (int mt = 0; mt < 4; mt++) {
        int x = x0 + xoff + mt * 16 + (l >> 2);
        #pragma unroll
        for (int nt = 0; nt < 4; nt++) {
            int n = nt * 8 + (l & 3) * 2;
            if (n < 28) {
                float* o = out + (size_t)(chbase + n) * IMG_HW + (size_t)y * IMG_W;
                o[x]              = acc[mt][nt][0];
                o[IMG_HW + x]     = acc[mt][nt][1];
                o[x + 8]          = acc[mt][nt][2];
                o[IMG_HW + x + 8] = acc[mt][nt][3];
            }
        }
    }
}

// ---------------------------------------------------------------------------
// Lowpass: 4x4 box mean -> bilinear upsample (exact fp32)
// ---------------------------------------------------------------------------
__global__ void __launch_bounds__(256)
nsst_downsample_kernel(const float* __restrict__ img)
{
    int idx = blockIdx.x * 256 + threadIdx.x;
    if (idx >= 4 * 3 * 128 * 128) return;
    int X = idx & 127, Y = (idx >> 7) & 127, bc = idx >> 14;
    const float* src = img + (size_t)bc * IMG_HW + (Y * 4) * IMG_W + X * 4;
    float s = 0.0f;
    #pragma unroll
    for (int i = 0; i < 4; i++) {
        float4 r = *reinterpret_cast<const float4*>(src + i * IMG_W);
        s += r.x + r.y + r.z + r.w;
    }
    g_low[idx] = s * (1.0f / 16.0f);
}

__global__ void __launch_bounds__(256)
nsst_upsample_kernel(float* __restrict__ out)
{
    int idx = blockIdx.x * 256 + threadIdx.x;
    if (idx >= 4 * 3 * IMG_HW) return;
    int x = idx & 511, y = (idx >> 9) & 511, bc = idx >> 18;
    int b = bc / 3, c = bc % 3;
    float sy = y * 0.25f - 0.375f;          // (y+0.5)/4 - 0.5
    float sx = x * 0.25f - 0.375f;
    int iy0 = (int)floorf(sy), ix0 = (int)floorf(sx);
    float fy = sy - (float)iy0, fx = sx - (float)ix0;
    int y0c = max(0, min(127, iy0)),  y1c = max(0, min(127, iy0 + 1));
    int x0c = max(0, min(127, ix0)),  x1c = max(0, min(127, ix0 + 1));
    const float* L = g_low + bc * 128 * 128;
    float v00 = L[y0c * 128 + x0c], v01 = L[y0c * 128 + x1c];
    float v10 = L[y1c * 128 + x0c], v11 = L[y1c * 128 + x1c];
    float top = v00 + fx * (v01 - v00);
    float bot = v10 + fx * (v11 - v10);
    out[((size_t)(b * 87 + c * 29 + 28) * IMG_W + y) * IMG_W + x] = top + fy * (bot - top);
}

// ---------------------------------------------------------------------------
extern "C" void kernel_launch(void* const* d_in, const int* in_sizes, int n_in,
                              void* d_out, int out_size)
{
    const float* img = (const float*)d_in[0];
    const float* f0  = (const float*)d_in[1];
    const float* f1  = (const float*)d_in[2];
    const float* f2  = (const float*)d_in[3];
    float* out = (float*)d_out;

    cudaFuncSetAttribute(nsst_mma_conv,
                         cudaFuncAttributeMaxDynamicSharedMemorySize, SMEM_TOTAL);

    nsst_prep<<<(3 * NG * 4 * 64 + 255) / 256, 256>>>(f0, f1, f2);

    dim3 grid(4, 128, 12);
    nsst_mma_conv<<<grid, 256, SMEM_TOTAL>>>(img, out);

    nsst_downsample_kernel<<<(4 * 3 * 128 * 128 + 255) / 256, 256>>>(img);
    nsst_upsample_kernel<<<(4 * 3 * IMG_HW + 255) / 256, 256>>>(out);
}

// round 9
// speedup vs baseline: 7.0103x; 1.6327x over previous
#include <cuda_runtime.h>
#include <cuda_fp16.h>
#include <cstdint>

// NSSTDecomposition via fp16 m16n8k16 mma.sync, per-scale implicit-GEMM split.
// s2: K=19x20(pad)=380->384, N=16 ; s1: K=15x16=240, N=8 ; s0: K=11x12=132->144, N=8.
// A read on the fly from an f16 window tile (duplicate 1-shifted copy solves the
// odd-pixel-lane alignment for f16 k-pairs). B staged in fragment order by prep.

#define IMG_W   512
#define IMG_HW  (512*512)
#define WROWS   23
#define WCOLS   152
#define WELEMS  (WROWS*WCOLS)      // 3496

// fragment slots per color: s2: 24g*2nt=48, s1: 15, s0: 9  => 72
#define SLOTS   72
#define SLOT_S1 48
#define SLOT_S0 63

__device__ float g_low[4*3*128*128];
__device__ uint2 g_bfrag[3*SLOTS*32];

__device__ __forceinline__ void mma_f16(float* d,
    uint32_t a0, uint32_t a1, uint32_t a2, uint32_t a3, uint32_t b0, uint32_t b1) {
    asm volatile("mma.sync.aligned.m16n8k16.row.col.f32.f16.f16.f32 "
                 "{%0,%1,%2,%3}, {%4,%5,%6,%7}, {%8,%9}, {%0,%1,%2,%3};"
                 : "+f"(d[0]), "+f"(d[1]), "+f"(d[2]), "+f"(d[3])
                 : "r"(a0), "r"(a1), "r"(a2), "r"(a3), "r"(b0), "r"(b1));
}

// ---------------------------------------------------------------------------
// Prep: weights -> f16 fragment image. Lane l of slot: n_row=l>>2, k pair base
// kq=(l&3)*2 ; b0 = {W[n][k0],W[n][k0+1]}, b1 = {W[n][k0+8],W[n][k0+9]}.
// ---------------------------------------------------------------------------
__global__ void __launch_bounds__(256)
nsst_prep(const float* __restrict__ f0, const float* __restrict__ f1,
          const float* __restrict__ f2)
{
    int i = blockIdx.x * 256 + threadIdx.x;          // 3*72*32 = 6912
    if (i >= 3 * SLOTS * 32) return;
    int l    = i & 31;
    int slot = (i >> 5) % SLOTS;
    int c    = i / (SLOTS * 32);
    int nr   = l >> 2;
    int kq   = (l & 3) * 2;

    uint32_t pk[2];
    #pragma unroll
    for (int r = 0; r < 2; r++) {
        int g, k;
        float v0 = 0.0f, v1 = 0.0f;
        if (slot < SLOT_S1) {                         // scale2: 19x19, PADW=20
            g = slot >> 1;
            int nt = slot & 1, nl = nt * 8 + nr;
            k = g * 16 + kq + r * 8;
            int dy = k / 20, dx = k - dy * 20;
            if (dy < 19 && nl < 16) {
                const float* fp = f2 + (size_t)(c * 16 + nl) * 361 + dy * 19 + dx;
                if (dx < 19)     v0 = fp[0];
                if (dx + 1 < 19) v1 = fp[1];
            }
        } else if (slot < SLOT_S0) {                  // scale1: 15x15, PADW=16
            g = slot - SLOT_S1;
            k = g * 16 + kq + r * 8;
            int dy = k >> 4, dx = k & 15;
            const float* fp = f1 + (size_t)(c * 8 + nr) * 225 + dy * 15 + dx;
            if (dx < 15)     v0 = fp[0];
            if (dx + 1 < 15) v1 = fp[1];
        } else {                                      // scale0: 11x11, PADW=12
            g = slot - SLOT_S0;
            k = g * 16 + kq + r * 8;
            int dy = k / 12, dx = k - dy * 12;
            if (dy < 11 && nr < 4) {
                const float* fp = f0 + (size_t)(c * 4 + nr) * 121 + dy * 11 + dx;
                if (dx < 11)     v0 = fp[0];
                if (dx + 1 < 11) v1 = fp[1];
            }
        }
        __half2 hh = __halves2half2(__float2half_rn(v0), __float2half_rn(v1));
        pk[r] = *reinterpret_cast<uint32_t*>(&hh);
    }
    g_bfrag[i] = make_uint2(pk[0], pk[1]);
}

// ---------------------------------------------------------------------------
// One scale: NG groups of k16, NT n8-tiles, 4 m16-tiles per warp.
// ---------------------------------------------------------------------------
template<int PADW, int RS, int NT, int NG, int NREAL, int CH0>
__device__ __forceinline__ void run_scale(
    const uint2* __restrict__ sb, const char* __restrict__ abase,
    float* __restrict__ obase,          // out + chbase*HW + y*512
    int l, int row_w, int xoff, int x0)
{
    const int roff = 9 - RS;
    const int px   = l >> 2;
    const int kq   = (l & 3) * 2;

    float acc[4][NT][4];
    #pragma unroll
    for (int mt = 0; mt < 4; mt++)
        #pragma unroll
        for (int nt = 0; nt < NT; nt++)
            #pragma unroll
            for (int q = 0; q < 4; q++) acc[mt][nt][q] = 0.0f;

    #pragma unroll 1
    for (int g = 0; g < NG; g++) {
        int k0 = g * 16 + kq;
        int k1 = k0 + 8;
        int dy0 = k0 / PADW, dx0 = k0 - dy0 * PADW;
        int dy1 = k1 / PADW, dx1 = k1 - dy1 * PADW;
        int e0 = (roff + row_w + dy0) * WCOLS + roff + xoff + px + dx0;
        int e1 = (roff + row_w + dy1) * WCOLS + roff + xoff + px + dx1;

        uint2 bf[NT];
        #pragma unroll
        for (int nt = 0; nt < NT; nt++) bf[nt] = sb[(g * NT + nt) * 32 + l];

        #pragma unroll
        for (int mt = 0; mt < 4; mt++) {
            uint32_t a0 = *(const uint32_t*)(abase + (size_t)(e0 + mt * 16) * 2);
            uint32_t a1 = *(const uint32_t*)(abase + (size_t)(e0 + mt * 16 + 8) * 2);
            uint32_t a2 = *(const uint32_t*)(abase + (size_t)(e1 + mt * 16) * 2);
            uint32_t a3 = *(const uint32_t*)(abase + (size_t)(e1 + mt * 16 + 8) * 2);
            #pragma unroll
            for (int nt = 0; nt < NT; nt++)
                mma_f16(acc[mt][nt], a0, a1, a2, a3, bf[nt].x, bf[nt].y);
        }
    }

    const int n2 = kq;                    // (l&3)*2
    #pragma unroll
    for (int mt = 0; mt < 4; mt++) {
        int x = xoff + mt * 16 + px + x0;
        #pragma unroll
        for (int nt = 0; nt < NT; nt++) {
            int n = nt * 8 + n2;
            if (n < NREAL) {
                float* o = obase + (size_t)(CH0 + n) * IMG_HW;
                o[x]              = acc[mt][nt][0];
                o[IMG_HW + x]     = acc[mt][nt][1];
                o[x + 8]          = acc[mt][nt][2];
                o[IMG_HW + x + 8] = acc[mt][nt][3];
            }
        }
    }
}

// ---------------------------------------------------------------------------
// Conv: grid (4 x-tiles, 128 y-quads, 12 bc), 256 threads = 8 warps.
// Warp w: y-row = w>>1, x-half = (w&1)*64; 64 px x all dirs per warp.
// ---------------------------------------------------------------------------
__global__ void __launch_bounds__(256)
nsst_mma_conv(const float* __restrict__ img, float* __restrict__ out)
{
    __shared__ uint2 s_b[SLOTS * 32];                         // 18432 B
    __shared__ __align__(16) __half s_winA[WELEMS];           //  6992 B
    __shared__ __align__(16) __half s_winB[WELEMS];           //  6992 B (shift-1)

    const int tid = threadIdx.x;
    const int l   = tid & 31;
    const int w   = tid >> 5;
    const int x0  = blockIdx.x * 128;
    const int y0  = blockIdx.y * 4;
    const int bz  = blockIdx.z, b = bz / 3, c = bz % 3;

    // stage B fragments
    {
        const uint2* src = g_bfrag + (size_t)c * SLOTS * 32;
        for (int i = tid; i < SLOTS * 32; i += 256) s_b[i] = src[i];
    }
    // stage window (f16) + shifted copy, zero-padded
    {
        const float* src = img + (size_t)bz * IMG_HW;
        for (int i = tid; i < WELEMS; i += 256) {
            int iy = i / WCOLS, ix = i - iy * WCOLS;
            int gy = y0 + iy - 9, gx = x0 + ix - 9;
            float v = 0.0f;
            if ((unsigned)gy < 512u && (unsigned)gx < 512u) v = src[gy * IMG_W + gx];
            __half h = __float2half_rn(v);
            s_winA[i] = h;
            if (i > 0) s_winB[i - 1] = h;
        }
    }
    __syncthreads();

    const int row_w = w >> 1;
    const int xoff  = (w & 1) * 64;
    const char* abase = ((l >> 2) & 1) ? ((const char*)s_winB - 2)
                                       : (const char*)s_winA;
    float* obase = out + (size_t)(b * 87 + c * 29) * IMG_HW
                       + (size_t)(y0 + row_w) * IMG_W;

    run_scale<20, 9, 2, 24, 16, 12>(s_b,                 abase, obase, l, row_w, xoff, x0);
    run_scale<16, 7, 1, 15,  8,  4>(s_b + SLOT_S1 * 32,  abase, obase, l, row_w, xoff, x0);
    run_scale<12, 5, 1,  9,  4,  0>(s_b + SLOT_S0 * 32,  abase, obase, l, row_w, xoff, x0);
}

// ---------------------------------------------------------------------------
// Lowpass: 4x4 box mean -> bilinear upsample (exact fp32)
// ---------------------------------------------------------------------------
__global__ void __launch_bounds__(256)
nsst_downsample_kernel(const float* __restrict__ img)
{
    int idx = blockIdx.x * 256 + threadIdx.x;
    if (idx >= 4 * 3 * 128 * 128) return;
    int X = idx & 127, Y = (idx >> 7) & 127, bc = idx >> 14;
    const float* src = img + (size_t)bc * IMG_HW + (Y * 4) * IMG_W + X * 4;
    float s = 0.0f;
    #pragma unroll
    for (int i = 0; i < 4; i++) {
        float4 r = *reinterpret_cast<const float4*>(src + i * IMG_W);
        s += r.x + r.y + r.z + r.w;
    }
    g_low[idx] = s * (1.0f / 16.0f);
}

__global__ void __launch_bounds__(256)
nsst_upsample_kernel(float* __restrict__ out)
{
    int idx = blockIdx.x * 256 + threadIdx.x;
    if (idx >= 4 * 3 * IMG_HW) return;
    int x = idx & 511, y = (idx >> 9) & 511, bc = idx >> 18;
    int b = bc / 3, c = bc % 3;
    float sy = y * 0.25f - 0.375f;          // (y+0.5)/4 - 0.5
    float sx = x * 0.25f - 0.375f;
    int iy0 = (int)floorf(sy), ix0 = (int)floorf(sx);
    float fy = sy - (float)iy0, fx = sx - (float)ix0;
    int y0c = max(0, min(127, iy0)),  y1c = max(0, min(127, iy0 + 1));
    int x0c = max(0, min(127, ix0)),  x1c = max(0, min(127, ix0 + 1));
    const float* L = g_low + bc * 128 * 128;
    float v00 = L[y0c * 128 + x0c], v01 = L[y0c * 128 + x1c];
    float v10 = L[y1c * 128 + x0c], v11 = L[y1c * 128 + x1c];
    float top = v00 + fx * (v01 - v00);
    float bot = v10 + fx * (v11 - v10);
    out[((size_t)(b * 87 + c * 29 + 28) * IMG_W + y) * IMG_W + x] = top + fy * (bot - top);
}

// ---------------------------------------------------------------------------
extern "C" void kernel_launch(void* const* d_in, const int* in_sizes, int n_in,
                              void* d_out, int out_size)
{
    const float* img = (const float*)d_in[0];
    const float* f0  = (const float*)d_in[1];
    const float* f1  = (const float*)d_in[2];
    const float* f2  = (const float*)d_in[3];
    float* out = (float*)d_out;

    nsst_prep<<<(3 * SLOTS * 32 + 255) / 256, 256>>>(f0, f1, f2);

    dim3 grid(4, 128, 12);
    nsst_mma_conv<<<grid, 256>>>(img, out);

    nsst_downsample_kernel<<<(4 * 3 * 128 * 128 + 255) / 256, 256>>>(img);
    nsst_upsample_kernel<<<(4 * 3 * IMG_HW + 255) / 256, 256>>>(out);
}